// round 12
// baseline (speedup 1.0000x reference)
#include <cuda_runtime.h>
#include <cuda_fp16.h>
#include <cstdint>

// ---------------- problem constants ----------------
#define B_ROWS 16384
#define D_FEAT 256
#define H_HID  64
#define O_OUT  256

// ---------------- device scratch (static, allocation-free) ----------------
__device__ __half g_u[(size_t)B_ROWS * D_FEAT];      // 8.4 MB fp16 u
__device__ __half g_wc[(size_t)O_OUT * D_FEAT];      // Wc fp16
__device__ float  g_knot[D_FEAT * 64];
__device__ float  g_slope[D_FEAT * 65];
__device__ float  g_inter[D_FEAT * 65];
__device__ unsigned int g_tabf[8];                   // per-dgroup ready flags

__device__ __forceinline__ uint32_t smem_u32(const void* p) {
    uint32_t a;
    asm("{ .reg .u64 t; cvta.to.shared.u64 t, %1; cvt.u32.u64 %0, t; }"
        : "=r"(a) : "l"(p));
    return a;
}

// =====================================================================
// Builder: one CTA per dgroup builds PWL tables for 32 features in smem
// (2 per warp), mirrors to gmem, raises the flag. __noinline__ so its
// register fat spills locally instead of inflating the eval path.
// =====================================================================
__device__ __noinline__
void build_tables(const float* __restrict__ W1,
                  const float* __restrict__ b1,
                  const float* __restrict__ W2,
                  const float* __restrict__ b2,
                  int d0, float* skt, float* ssl, float* sin_,
                  float* stage, int dgroup)
{
    const int tid = threadIdx.x;
    const int wid = tid >> 5;
    const int lid = tid & 31;
    float* st = stage + wid * 64;

    #pragma unroll 1
    for (int f = 0; f < 2; f++) {
        const int fd = wid * 2 + f;
        const int dg = d0 + fd;

        float t[2], ds[2], di[2];
        float bs = 0.0f, bi = 0.0f;
        #pragma unroll
        for (int i = 0; i < 2; i++) {
            const int h  = lid + i * 32;
            const float w1 = W1[dg * H_HID + h];
            const float bb = b1[dg * H_HID + h];
            const float w2 = W2[dg * H_HID + h];
            if (w1 != 0.0f) {
                t[i]  = -bb / w1;
                ds[i] = fabsf(w1) * w2;
                di[i] = (w1 > 0.0f) ? (w2 * bb) : (-w2 * bb);
                if (w1 < 0.0f) { bs += w1 * w2; bi += w2 * bb; }
            } else {
                t[i]  = __int_as_float(0x7f800000);   // +inf
                ds[i] = 0.0f;
                di[i] = 0.0f;
                bi   += w2 * fmaxf(bb, 0.0f);
            }
            st[h] = t[i];
        }
        #pragma unroll
        for (int off = 16; off >= 1; off >>= 1) {
            bs += __shfl_xor_sync(0xffffffffu, bs, off);
            bi += __shfl_xor_sync(0xffffffffu, bi, off);
        }
        bi += b2[dg];

        __syncwarp();
        int r0 = 0, r1 = 0;
        const float t0 = t[0], t1 = t[1];
        #pragma unroll 16
        for (int j = 0; j < 64; j++) {
            float tj = st[j];
            r0 += (tj < t0) || (tj == t0 && j < lid);
            r1 += (tj < t1) || (tj == t1 && j < lid + 32);
        }
        // scatter sorted knots + deltas directly into table rows
        skt[fd * 65 + r0]  = t0;    skt[fd * 65 + r1]  = t1;
        ssl[fd * 65 + r0]  = ds[0]; ssl[fd * 65 + r1]  = ds[1];
        sin_[fd * 65 + r0] = di[0]; sin_[fd * 65 + r1] = di[1];
        __syncwarp();

        // inclusive scan of sorted deltas -> slope/intercept tables
        const float v0s = ssl[fd * 65 + 2 * lid];
        const float v1s = ssl[fd * 65 + 2 * lid + 1];
        const float v0i = sin_[fd * 65 + 2 * lid];
        const float v1i = sin_[fd * 65 + 2 * lid + 1];
        float incs = v0s + v1s, inci = v0i + v1i;
        const float ps = incs, pi = inci;
        #pragma unroll
        for (int off = 1; off < 32; off <<= 1) {
            float as_ = __shfl_up_sync(0xffffffffu, incs, off);
            float ai_ = __shfl_up_sync(0xffffffffu, inci, off);
            if (lid >= off) { incs += as_; inci += ai_; }
        }
        const float exs = incs - ps, exi = inci - pi;
        __syncwarp();   // all scan reads done before overwrite

        if (lid == 0) {
            ssl[fd * 65]  = bs;
            sin_[fd * 65] = bi;
        }
        ssl[fd * 65 + 2 * lid + 1]  = bs + exs + v0s;
        sin_[fd * 65 + 2 * lid + 1] = bi + exi + v0i;
        ssl[fd * 65 + 2 * lid + 2]  = bs + incs;
        sin_[fd * 65 + 2 * lid + 2] = bi + inci;
        __syncwarp();
    }
    __syncthreads();

    // mirror tables to gmem for the other 63 CTAs of this dgroup
    for (int i = tid; i < 32 * 64; i += 512) {
        int d2 = i >> 6, j = i & 63;
        g_knot[(d0 + d2) * 64 + j] = skt[d2 * 65 + j];
    }
    for (int i = tid; i < 32 * 65; i += 512) {
        int d2 = i / 65, k = i % 65;
        g_slope[(d0 + d2) * 65 + k] = ssl[d2 * 65 + k];
        g_inter[(d0 + d2) * 65 + k] = sin_[d2 * 65 + k];
    }
    __threadfence();
    __syncthreads();
    if (tid == 0) atomicExch(&g_tabf[dgroup], 1u);
}

// =====================================================================
// Kernel 1: eval u with inline table build (8 builder CTAs) + Wc slice.
// grid = (64 rowchunks, 8 dgroups) = 512 CTAs, 512 threads.
// __launch_bounds__(512, 3): pins >=3 CTAs/SM so the eval path stays
// spill-free (~42 reg cap); builder spills are confined to 8 CTAs.
// =====================================================================
__global__ __launch_bounds__(512, 3)
void eval_u_kernel(const float* __restrict__ x,
                   const float* __restrict__ W1,
                   const float* __restrict__ b1,
                   const float* __restrict__ W2,
                   const float* __restrict__ b2,
                   const float* __restrict__ Wc)
{
    __shared__ float skt[32 * 65];
    __shared__ float ssl[32 * 65];
    __shared__ float sin_[32 * 65];
    __shared__ float stage[16 * 64];     // builder t-staging (4KB)

    const int tid = threadIdx.x;
    const int d0  = blockIdx.y * 32;

    // ---- Wc convert slice: 32 float4 per CTA, exact partition ----
    if (tid < 32) {
        const float4* W4 = reinterpret_cast<const float4*>(Wc);
        int idx = (blockIdx.y * 64 + blockIdx.x) * 32 + tid;
        float4 f = W4[idx];
        __half2 h0 = __float22half2_rn(make_float2(f.x, f.y));
        __half2 h1 = __float22half2_rn(make_float2(f.z, f.w));
        uint2 pk;
        pk.x = *reinterpret_cast<uint32_t*>(&h0);
        pk.y = *reinterpret_cast<uint32_t*>(&h1);
        *reinterpret_cast<uint2*>(&g_wc[idx * 4]) = pk;
    }

    const int dd  = tid & 31;
    const int bl  = tid >> 5;
    const int d   = d0 + dd;
    const int ddk = dd * 65;
    const int rowbase = blockIdx.x * 256;

    // ---- prefetch batch-1 x (8 LDG in flight across build/spin) ----
    float xv0[8];
    #pragma unroll
    for (int j = 0; j < 8; j++)
        xv0[j] = __ldg(&x[(size_t)(rowbase + bl + j * 16) * D_FEAT + d]);

    if (blockIdx.x == 0) {
        build_tables(W1, b1, W2, b2, d0, skt, ssl, sin_, stage, blockIdx.y);
        // smem tables valid + __syncthreads done inside
    } else {
        if (tid == 0) {
            while (((volatile unsigned int*)g_tabf)[blockIdx.y] == 0u)
                __nanosleep(32);
            __threadfence();
        }
        __syncthreads();
        for (int i = tid; i < 32 * 64; i += 512) {
            int d2 = i >> 6, j = i & 63;
            skt[d2 * 65 + j] = g_knot[(d0 + d2) * 64 + j];
        }
        for (int i = tid; i < 32 * 65; i += 512) {
            int d2 = i / 65, k = i % 65;
            ssl[d2 * 65 + k]  = g_slope[(d0 + d2) * 65 + k];
            sin_[d2 * 65 + k] = g_inter[(d0 + d2) * 65 + k];
        }
        __syncthreads();
    }

    // ---- level-1 pivots in registers ----
    float pv[8];
    #pragma unroll
    for (int g = 0; g < 8; g++) pv[g] = skt[ddk + g * 8 + 7];

    // ---- batch 1 (prefetched) ----
    {
        int lo[8];
        #pragma unroll
        for (int j = 0; j < 8; j++) {
            const float xj = xv0[j];
            int g = 0;
            #pragma unroll
            for (int gg = 0; gg < 8; gg++) g += (pv[gg] < xj);
            const int gm = ((g < 8) ? g : 7) << 3;
            const float* kb = &skt[ddk + gm];
            int l2 = (kb[3] < xj) ? 4 : 0;
            l2 += (kb[l2 + 1] < xj) ? 2 : 0;
            l2 += (kb[l2] < xj) ? 1 : 0;
            lo[j] = (g < 8) ? (gm + l2) : 64;
        }
        #pragma unroll
        for (int j = 0; j < 8; j++) {
            float u = fmaf(ssl[ddk + lo[j]], xv0[j], sin_[ddk + lo[j]]);
            g_u[(size_t)(rowbase + bl + j * 16) * D_FEAT + d] = __float2half(u);
        }
    }
    // ---- batch 2 ----
    {
        const int rb = rowbase + 128 + bl;
        float xv[8];
        #pragma unroll
        for (int j = 0; j < 8; j++)
            xv[j] = __ldg(&x[(size_t)(rb + j * 16) * D_FEAT + d]);

        int lo[8];
        #pragma unroll
        for (int j = 0; j < 8; j++) {
            const float xj = xv[j];
            int g = 0;
            #pragma unroll
            for (int gg = 0; gg < 8; gg++) g += (pv[gg] < xj);
            const int gm = ((g < 8) ? g : 7) << 3;
            const float* kb = &skt[ddk + gm];
            int l2 = (kb[3] < xj) ? 4 : 0;
            l2 += (kb[l2 + 1] < xj) ? 2 : 0;
            l2 += (kb[l2] < xj) ? 1 : 0;
            lo[j] = (g < 8) ? (gm + l2) : 64;
        }
        #pragma unroll
        for (int j = 0; j < 8; j++) {
            float u = fmaf(ssl[ddk + lo[j]], xv[j], sin_[ddk + lo[j]]);
            g_u[(size_t)(rb + j * 16) * D_FEAT + d] = __float2half(u);
        }
    }
}

// =====================================================================
// Kernel 2: GEMM out = u @ Wc^T + bc, M=128 x N=256 x K=256 (R11).
// 256 threads = 8 warps (2m x 4n), warp tile 64x64, 4-stage prefetch.
// Also resets table flags for the next graph replay.
// =====================================================================
#define CH      64
#define CH_PAD  72
#define A_ST_H  (128 * CH_PAD)
#define B_ST_H  (256 * CH_PAD)
#define N_STAGE 4
#define GEMM_SMEM_BYTES ((A_ST_H + B_ST_H) * 2 * N_STAGE)   // 221184
#define GTHREADS 256

__device__ __forceinline__ void cp16(uint32_t dst, const void* src) {
    asm volatile("cp.async.cg.shared.global [%0], [%1], 16;"
                 :: "r"(dst), "l"(src));
}
#define CP_COMMIT() asm volatile("cp.async.commit_group;" ::: "memory")
#define CP_WAIT(n)  asm volatile("cp.async.wait_group %0;" :: "n"(n) : "memory")

__device__ __forceinline__ void ldsm_x4(uint32_t* r, uint32_t addr) {
    asm volatile("ldmatrix.sync.aligned.m8n8.x4.shared.b16 {%0,%1,%2,%3}, [%4];"
                 : "=r"(r[0]), "=r"(r[1]), "=r"(r[2]), "=r"(r[3]) : "r"(addr));
}
__device__ __forceinline__ void mma_16816(float* c, const uint32_t* a,
                                          const uint32_t* b) {
    asm volatile(
        "mma.sync.aligned.m16n8k16.row.col.f32.f16.f16.f32 "
        "{%0,%1,%2,%3}, {%4,%5,%6,%7}, {%8,%9}, {%0,%1,%2,%3};"
        : "+f"(c[0]), "+f"(c[1]), "+f"(c[2]), "+f"(c[3])
        : "r"(a[0]), "r"(a[1]), "r"(a[2]), "r"(a[3]), "r"(b[0]), "r"(b[1]));
}

struct GemmCtx {
    uint32_t as_u32, bs_u32;
    const __half* Asrc;
    int tid;
};

__device__ __forceinline__ void issue_chunk(const GemmCtx& g, int c, int st) {
    #pragma unroll
    for (int i = 0; i < 4; i++) {
        int idx = g.tid + i * GTHREADS;
        int row = idx >> 3, k8 = idx & 7;
        cp16(g.as_u32 + (uint32_t)((st * A_ST_H + row * CH_PAD + k8 * 8) * 2),
             g.Asrc + row * D_FEAT + c * CH + k8 * 8);
    }
    #pragma unroll
    for (int i = 0; i < 8; i++) {
        int idx = g.tid + i * GTHREADS;
        int row = idx >> 3, k8 = idx & 7;
        cp16(g.bs_u32 + (uint32_t)((st * B_ST_H + row * CH_PAD + k8 * 8) * 2),
             g_wc + row * D_FEAT + c * CH + k8 * 8);
    }
}

__global__ __launch_bounds__(GTHREADS, 1)
void gemm_kernel(const float* __restrict__ bc, float* __restrict__ out)
{
    extern __shared__ __half smem[];
    __half* As = smem;
    __half* Bs = smem + N_STAGE * A_ST_H;

    const int tid = threadIdx.x;
    const int wid = tid >> 5;
    const int lid = tid & 31;
    const int m0  = blockIdx.x * 128;

    // reset eval flags for next graph replay (stream-ordered: safe)
    if (blockIdx.x == 0 && tid < 8) g_tabf[tid] = 0u;

    GemmCtx g;
    g.as_u32 = smem_u32(As);
    g.bs_u32 = smem_u32(Bs);
    g.Asrc   = g_u + (size_t)m0 * D_FEAT;
    g.tid    = tid;

    issue_chunk(g, 0, 0); CP_COMMIT();
    issue_chunk(g, 1, 1); CP_COMMIT();
    issue_chunk(g, 2, 2); CP_COMMIT();
    issue_chunk(g, 3, 3); CP_COMMIT();

    const int warp_m = wid >> 2;   // 0..1
    const int warp_n = wid & 3;    // 0..3

    const int a_row = warp_m * 64 + (lid & 15);
    const uint32_t a_lane = g.as_u32
        + (uint32_t)((a_row * CH_PAD + ((lid >> 4) << 3)) * 2);
    const int b_row = warp_n * 64 + (((lid >> 4) & 1) << 3) + (lid & 7);
    const uint32_t b_lane = g.bs_u32
        + (uint32_t)((b_row * CH_PAD + (((lid >> 3) & 1) << 3)) * 2);

    float acc[4][8][4];
    #pragma unroll
    for (int i = 0; i < 4; i++)
        #pragma unroll
        for (int j = 0; j < 8; j++)
            #pragma unroll
            for (int q = 0; q < 4; q++) acc[i][j][q] = 0.0f;

    #pragma unroll
    for (int c = 0; c < 4; c++) {
        if      (c == 0) { CP_WAIT(3); }
        else if (c == 1) { CP_WAIT(2); }
        else if (c == 2) { CP_WAIT(1); }
        else             { CP_WAIT(0); }
        __syncthreads();

        const uint32_t a_st = a_lane + (uint32_t)(c * A_ST_H * 2);
        const uint32_t b_st = b_lane + (uint32_t)(c * B_ST_H * 2);

        #pragma unroll
        for (int ks = 0; ks < 4; ks++) {
            const uint32_t kb = (uint32_t)(ks * 32);
            uint32_t afr[4][4];
            #pragma unroll
            for (int tm = 0; tm < 4; tm++)
                ldsm_x4(afr[tm], a_st + (uint32_t)(tm * 16 * CH_PAD * 2) + kb);
            uint32_t bfr[8][2];
            #pragma unroll
            for (int pn = 0; pn < 4; pn++) {
                uint32_t q[4];
                ldsm_x4(q, b_st + (uint32_t)(pn * 16 * CH_PAD * 2) + kb);
                bfr[2 * pn][0]     = q[0];
                bfr[2 * pn][1]     = q[1];
                bfr[2 * pn + 1][0] = q[2];
                bfr[2 * pn + 1][1] = q[3];
            }
            #pragma unroll
            for (int tm = 0; tm < 4; tm++)
                #pragma unroll
                for (int tn = 0; tn < 8; tn++)
                    mma_16816(acc[tm][tn], afr[tm], bfr[tn]);
        }
    }

    const int qr = lid >> 2;
    const int qc = (lid & 3) * 2;
    #pragma unroll
    for (int tn = 0; tn < 8; tn++) {
        const int cb = warp_n * 64 + tn * 8 + qc;
        const float2 bcv = *reinterpret_cast<const float2*>(bc + cb);
        #pragma unroll
        for (int tm = 0; tm < 4; tm++) {
            const int r = m0 + warp_m * 64 + tm * 16 + qr;
            float2 v0, v1;
            v0.x = acc[tm][tn][0] + bcv.x;
            v0.y = acc[tm][tn][1] + bcv.y;
            v1.x = acc[tm][tn][2] + bcv.x;
            v1.y = acc[tm][tn][3] + bcv.y;
            *reinterpret_cast<float2*>(out + (size_t)r * O_OUT + cb) = v0;
            *reinterpret_cast<float2*>(out + (size_t)(r + 8) * O_OUT + cb) = v1;
        }
    }
}

// =====================================================================
// launch
// =====================================================================
extern "C" void kernel_launch(void* const* d_in, const int* in_sizes, int n_in,
                              void* d_out, int out_size)
{
    const float* x  = (const float*)d_in[0];
    const float* W1 = (const float*)d_in[1];
    const float* b1 = (const float*)d_in[2];
    const float* W2 = (const float*)d_in[3];
    const float* b2 = (const float*)d_in[4];
    const float* Wc = (const float*)d_in[5];
    const float* bc = (const float*)d_in[6];
    float* out = (float*)d_out;

    eval_u_kernel<<<dim3(B_ROWS / 256, D_FEAT / 32), 512>>>(
        x, W1, b1, W2, b2, Wc);
    gemm_kernel<<<B_ROWS / 128, GTHREADS, GEMM_SMEM_BYTES>>>(bc, out);
}

namespace {
struct AttrInit {
    AttrInit() {
        cudaFuncSetAttribute(gemm_kernel,
                             cudaFuncAttributeMaxDynamicSharedMemorySize,
                             GEMM_SMEM_BYTES);
    }
} g_attr_init;
}

// round 13
// speedup vs baseline: 1.1808x; 1.1808x over previous
#include <cuda_runtime.h>
#include <cuda_fp16.h>
#include <cstdint>

// ---------------- problem constants ----------------
#define B_ROWS 16384
#define D_FEAT 256
#define H_HID  64
#define O_OUT  256

// ---------------- device scratch (static, allocation-free) ----------------
__device__ __half g_u[(size_t)B_ROWS * D_FEAT];      // 8.4 MB fp16 u
__device__ __half g_wc[(size_t)O_OUT * D_FEAT];      // Wc fp16
__device__ float  g_knot[D_FEAT * 64];
__device__ float  g_slope[D_FEAT * 65];
__device__ float  g_inter[D_FEAT * 65];

__device__ __forceinline__ uint32_t smem_u32(const void* p) {
    uint32_t a;
    asm("{ .reg .u64 t; cvta.to.shared.u64 t, %1; cvt.u32.u64 %0, t; }"
        : "=r"(a) : "l"(p));
    return a;
}

// =====================================================================
// Kernel 1: PWL table build (blocks 0..63) + Wc fp16 convert (64..191).
// (R9/R11 kernel — measured ~5.8us, absorbs clock-ramp)
// =====================================================================
__global__ __launch_bounds__(128)
void prep_kernel(const float* __restrict__ W1,
                 const float* __restrict__ b1,
                 const float* __restrict__ W2,
                 const float* __restrict__ b2,
                 const float* __restrict__ Wc)
{
    const int bid = blockIdx.x;

    if (bid >= 64) {
        const float4* W4 = reinterpret_cast<const float4*>(Wc);
        int idx = (bid - 64) * 128 + threadIdx.x;
        float4 f = W4[idx];
        __half2 h0 = __float22half2_rn(make_float2(f.x, f.y));
        __half2 h1 = __float22half2_rn(make_float2(f.z, f.w));
        uint2 pk;
        pk.x = *reinterpret_cast<uint32_t*>(&h0);
        pk.y = *reinterpret_cast<uint32_t*>(&h1);
        *reinterpret_cast<uint2*>(&g_wc[idx * 4]) = pk;
        return;
    }

    const int w    = threadIdx.x >> 5;
    const int lane = threadIdx.x & 31;
    const int d    = bid * 4 + w;

    __shared__ float s_t[4][64], s_ds[4][64], s_di[4][64];
    __shared__ float s_kt[4][64], s_kds[4][64], s_kdi[4][64];

    float t[2], ds[2], di[2];
    float bs = 0.0f, bi = 0.0f;
    #pragma unroll
    for (int i = 0; i < 2; i++) {
        const int h  = lane + i * 32;
        const float w1 = W1[d * H_HID + h];
        const float bb = b1[d * H_HID + h];
        const float w2 = W2[d * H_HID + h];
        if (w1 != 0.0f) {
            t[i]  = -bb / w1;
            ds[i] = fabsf(w1) * w2;
            di[i] = (w1 > 0.0f) ? (w2 * bb) : (-w2 * bb);
            if (w1 < 0.0f) { bs += w1 * w2; bi += w2 * bb; }
        } else {
            t[i]  = __int_as_float(0x7f800000);
            ds[i] = 0.0f;
            di[i] = 0.0f;
            bi   += w2 * fmaxf(bb, 0.0f);
        }
        s_t[w][h]  = t[i];
        s_ds[w][h] = ds[i];
        s_di[w][h] = di[i];
    }
    #pragma unroll
    for (int off = 16; off >= 1; off >>= 1) {
        bs += __shfl_xor_sync(0xffffffffu, bs, off);
        bi += __shfl_xor_sync(0xffffffffu, bi, off);
    }
    bi += b2[d];

    __syncwarp();
    int r0 = 0, r1 = 0;
    const float t0 = t[0], t1 = t[1];
    #pragma unroll 16
    for (int j = 0; j < 64; j++) {
        float tj = s_t[w][j];
        r0 += (tj < t0) || (tj == t0 && j < lane);
        r1 += (tj < t1) || (tj == t1 && j < lane + 32);
    }
    s_kt[w][r0]  = t0;  s_kds[w][r0] = ds[0]; s_kdi[w][r0] = di[0];
    s_kt[w][r1]  = t1;  s_kds[w][r1] = ds[1]; s_kdi[w][r1] = di[1];
    __syncwarp();

    const float v0s = s_kds[w][2 * lane],     v1s = s_kds[w][2 * lane + 1];
    const float v0i = s_kdi[w][2 * lane],     v1i = s_kdi[w][2 * lane + 1];
    float incs = v0s + v1s, inci = v0i + v1i;
    const float ps = incs, pi = inci;
    #pragma unroll
    for (int off = 1; off < 32; off <<= 1) {
        float as_ = __shfl_up_sync(0xffffffffu, incs, off);
        float ai_ = __shfl_up_sync(0xffffffffu, inci, off);
        if (lane >= off) { incs += as_; inci += ai_; }
    }
    const float exs = incs - ps, exi = inci - pi;

    if (lane == 0) {
        g_slope[d * 65] = bs;
        g_inter[d * 65] = bi;
    }
    g_slope[d * 65 + 2 * lane + 1] = bs + exs + v0s;
    g_inter[d * 65 + 2 * lane + 1] = bi + exi + v0i;
    g_slope[d * 65 + 2 * lane + 2] = bs + incs;
    g_inter[d * 65 + 2 * lane + 2] = bi + inci;
    g_knot[d * 64 + 2 * lane]     = s_kt[w][2 * lane];
    g_knot[d * 64 + 2 * lane + 1] = s_kt[w][2 * lane + 1];
}

// =====================================================================
// Kernel 2: eval u — TRANSPOSED tables [idx][dd] (stride 32):
// lane bank = (idx*32 + dd) mod 32 = dd -> conflict-free for every
// data-dependent access (pivots, search steps, slope, intercept).
// grid = (64 rowchunks x 8 dgroups) = 512 CTAs, 512 threads, 4 CTA/SM.
// =====================================================================
__global__ __launch_bounds__(512)
void eval_u_kernel(const float* __restrict__ x)
{
    __shared__ float skt[64 * 32];    // [j][dd]
    __shared__ float ssl[65 * 32];    // [k][dd]
    __shared__ float sin_[65 * 32];   // [k][dd]

    const int tid = threadIdx.x;
    const int d0  = blockIdx.y * 32;

    // fill transposed: i&31 = dd, i>>5 = j -> STS bank = dd (conflict-free)
    for (int i = tid; i < 64 * 32; i += 512) {
        int dd = i & 31, j = i >> 5;
        skt[j * 32 + dd] = g_knot[(d0 + dd) * 64 + j];
    }
    for (int i = tid; i < 65 * 32; i += 512) {
        int dd = i & 31, k = i >> 5;
        ssl[k * 32 + dd]  = g_slope[(d0 + dd) * 65 + k];
        sin_[k * 32 + dd] = g_inter[(d0 + dd) * 65 + k];
    }
    __syncthreads();

    const int dd  = tid & 31;
    const int bl  = tid >> 5;
    const int d   = d0 + dd;
    const int rowbase = blockIdx.x * 256;

    // level-1 pivots in registers: knot[8g+7]
    float pv[8];
    #pragma unroll
    for (int g = 0; g < 8; g++) pv[g] = skt[(g * 8 + 7) * 32 + dd];

    #pragma unroll
    for (int batch = 0; batch < 2; batch++) {
        const int rb = rowbase + batch * 128 + bl;
        float xv[8];
        #pragma unroll
        for (int j = 0; j < 8; j++)
            xv[j] = __ldg(&x[(size_t)(rb + j * 16) * D_FEAT + d]);

        int lo[8];
        #pragma unroll
        for (int j = 0; j < 8; j++) {
            const float xj = xv[j];
            int g = 0;
            #pragma unroll
            for (int gg = 0; gg < 8; gg++) g += (pv[gg] < xj);
            const int gm = ((g < 8) ? g : 7) << 3;
            int l2 = (skt[(gm + 3) * 32 + dd] < xj) ? 4 : 0;
            l2 += (skt[(gm + l2 + 1) * 32 + dd] < xj) ? 2 : 0;
            l2 += (skt[(gm + l2) * 32 + dd] < xj) ? 1 : 0;
            lo[j] = (g < 8) ? (gm + l2) : 64;
        }
        #pragma unroll
        for (int j = 0; j < 8; j++) {
            float u = fmaf(ssl[lo[j] * 32 + dd], xv[j], sin_[lo[j] * 32 + dd]);
            g_u[(size_t)(rb + j * 16) * D_FEAT + d] = __float2half(u);
        }
    }
}

// =====================================================================
// Kernel 3: GEMM out = u @ Wc^T + bc, M=128 x N=256 x K=256 (R11 —
// measured 14.4us; insensitive to scheduling, leave as-is).
// 256 threads = 8 warps (2m x 4n), warp tile 64x64, 4-stage prefetch.
// =====================================================================
#define CH      64
#define CH_PAD  72
#define A_ST_H  (128 * CH_PAD)
#define B_ST_H  (256 * CH_PAD)
#define N_STAGE 4
#define GEMM_SMEM_BYTES ((A_ST_H + B_ST_H) * 2 * N_STAGE)   // 221184
#define GTHREADS 256

__device__ __forceinline__ void cp16(uint32_t dst, const void* src) {
    asm volatile("cp.async.cg.shared.global [%0], [%1], 16;"
                 :: "r"(dst), "l"(src));
}
#define CP_COMMIT() asm volatile("cp.async.commit_group;" ::: "memory")
#define CP_WAIT(n)  asm volatile("cp.async.wait_group %0;" :: "n"(n) : "memory")

__device__ __forceinline__ void ldsm_x4(uint32_t* r, uint32_t addr) {
    asm volatile("ldmatrix.sync.aligned.m8n8.x4.shared.b16 {%0,%1,%2,%3}, [%4];"
                 : "=r"(r[0]), "=r"(r[1]), "=r"(r[2]), "=r"(r[3]) : "r"(addr));
}
__device__ __forceinline__ void mma_16816(float* c, const uint32_t* a,
                                          const uint32_t* b) {
    asm volatile(
        "mma.sync.aligned.m16n8k16.row.col.f32.f16.f16.f32 "
        "{%0,%1,%2,%3}, {%4,%5,%6,%7}, {%8,%9}, {%0,%1,%2,%3};"
        : "+f"(c[0]), "+f"(c[1]), "+f"(c[2]), "+f"(c[3])
        : "r"(a[0]), "r"(a[1]), "r"(a[2]), "r"(a[3]), "r"(b[0]), "r"(b[1]));
}

struct GemmCtx {
    uint32_t as_u32, bs_u32;
    const __half* Asrc;
    int tid;
};

__device__ __forceinline__ void issue_chunk(const GemmCtx& g, int c, int st) {
    #pragma unroll
    for (int i = 0; i < 4; i++) {
        int idx = g.tid + i * GTHREADS;
        int row = idx >> 3, k8 = idx & 7;
        cp16(g.as_u32 + (uint32_t)((st * A_ST_H + row * CH_PAD + k8 * 8) * 2),
             g.Asrc + row * D_FEAT + c * CH + k8 * 8);
    }
    #pragma unroll
    for (int i = 0; i < 8; i++) {
        int idx = g.tid + i * GTHREADS;
        int row = idx >> 3, k8 = idx & 7;
        cp16(g.bs_u32 + (uint32_t)((st * B_ST_H + row * CH_PAD + k8 * 8) * 2),
             g_wc + row * D_FEAT + c * CH + k8 * 8);
    }
}

__global__ __launch_bounds__(GTHREADS, 1)
void gemm_kernel(const float* __restrict__ bc, float* __restrict__ out)
{
    extern __shared__ __half smem[];
    __half* As = smem;
    __half* Bs = smem + N_STAGE * A_ST_H;

    const int tid = threadIdx.x;
    const int wid = tid >> 5;
    const int lid = tid & 31;
    const int m0  = blockIdx.x * 128;

    GemmCtx g;
    g.as_u32 = smem_u32(As);
    g.bs_u32 = smem_u32(Bs);
    g.Asrc   = g_u + (size_t)m0 * D_FEAT;
    g.tid    = tid;

    issue_chunk(g, 0, 0); CP_COMMIT();
    issue_chunk(g, 1, 1); CP_COMMIT();
    issue_chunk(g, 2, 2); CP_COMMIT();
    issue_chunk(g, 3, 3); CP_COMMIT();

    const int warp_m = wid >> 2;   // 0..1
    const int warp_n = wid & 3;    // 0..3

    const int a_row = warp_m * 64 + (lid & 15);
    const uint32_t a_lane = g.as_u32
        + (uint32_t)((a_row * CH_PAD + ((lid >> 4) << 3)) * 2);
    const int b_row = warp_n * 64 + (((lid >> 4) & 1) << 3) + (lid & 7);
    const uint32_t b_lane = g.bs_u32
        + (uint32_t)((b_row * CH_PAD + (((lid >> 3) & 1) << 3)) * 2);

    float acc[4][8][4];
    #pragma unroll
    for (int i = 0; i < 4; i++)
        #pragma unroll
        for (int j = 0; j < 8; j++)
            #pragma unroll
            for (int q = 0; q < 4; q++) acc[i][j][q] = 0.0f;

    #pragma unroll
    for (int c = 0; c < 4; c++) {
        if      (c == 0) { CP_WAIT(3); }
        else if (c == 1) { CP_WAIT(2); }
        else if (c == 2) { CP_WAIT(1); }
        else             { CP_WAIT(0); }
        __syncthreads();

        const uint32_t a_st = a_lane + (uint32_t)(c * A_ST_H * 2);
        const uint32_t b_st = b_lane + (uint32_t)(c * B_ST_H * 2);

        #pragma unroll
        for (int ks = 0; ks < 4; ks++) {
            const uint32_t kb = (uint32_t)(ks * 32);
            uint32_t afr[4][4];
            #pragma unroll
            for (int tm = 0; tm < 4; tm++)
                ldsm_x4(afr[tm], a_st + (uint32_t)(tm * 16 * CH_PAD * 2) + kb);
            uint32_t bfr[8][2];
            #pragma unroll
            for (int pn = 0; pn < 4; pn++) {
                uint32_t q[4];
                ldsm_x4(q, b_st + (uint32_t)(pn * 16 * CH_PAD * 2) + kb);
                bfr[2 * pn][0]     = q[0];
                bfr[2 * pn][1]     = q[1];
                bfr[2 * pn + 1][0] = q[2];
                bfr[2 * pn + 1][1] = q[3];
            }
            #pragma unroll
            for (int tm = 0; tm < 4; tm++)
                #pragma unroll
                for (int tn = 0; tn < 8; tn++)
                    mma_16816(acc[tm][tn], afr[tm], bfr[tn]);
        }
    }

    const int qr = lid >> 2;
    const int qc = (lid & 3) * 2;
    #pragma unroll
    for (int tn = 0; tn < 8; tn++) {
        const int cb = warp_n * 64 + tn * 8 + qc;
        const float2 bcv = *reinterpret_cast<const float2*>(bc + cb);
        #pragma unroll
        for (int tm = 0; tm < 4; tm++) {
            const int r = m0 + warp_m * 64 + tm * 16 + qr;
            float2 v0, v1;
            v0.x = acc[tm][tn][0] + bcv.x;
            v0.y = acc[tm][tn][1] + bcv.y;
            v1.x = acc[tm][tn][2] + bcv.x;
            v1.y = acc[tm][tn][3] + bcv.y;
            *reinterpret_cast<float2*>(out + (size_t)r * O_OUT + cb) = v0;
            *reinterpret_cast<float2*>(out + (size_t)(r + 8) * O_OUT + cb) = v1;
        }
    }
}

// =====================================================================
// launch
// =====================================================================
extern "C" void kernel_launch(void* const* d_in, const int* in_sizes, int n_in,
                              void* d_out, int out_size)
{
    const float* x  = (const float*)d_in[0];
    const float* W1 = (const float*)d_in[1];
    const float* b1 = (const float*)d_in[2];
    const float* W2 = (const float*)d_in[3];
    const float* b2 = (const float*)d_in[4];
    const float* Wc = (const float*)d_in[5];
    const float* bc = (const float*)d_in[6];
    float* out = (float*)d_out;

    prep_kernel<<<192, 128>>>(W1, b1, W2, b2, Wc);
    eval_u_kernel<<<dim3(B_ROWS / 256, D_FEAT / 32), 512>>>(x);
    gemm_kernel<<<B_ROWS / 128, GTHREADS, GEMM_SMEM_BYTES>>>(bc, out);
}

namespace {
struct AttrInit {
    AttrInit() {
        cudaFuncSetAttribute(gemm_kernel,
                             cudaFuncAttributeMaxDynamicSharedMemorySize,
                             GEMM_SMEM_BYTES);
    }
} g_attr_init;
}

// round 14
// speedup vs baseline: 1.4481x; 1.2264x over previous
#include <cuda_runtime.h>
#include <cuda_fp16.h>
#include <cstdint>

// ---------------- problem constants ----------------
#define B_ROWS 16384
#define D_FEAT 256
#define H_HID  64
#define O_OUT  256

// ---------------- device scratch (static, allocation-free) ----------------
__device__ __half  g_u[(size_t)B_ROWS * D_FEAT];     // 8.4 MB fp16 u
__device__ __half  g_wc[(size_t)O_OUT * D_FEAT];     // Wc fp16
// transposed tables: [dgroup][idx][dd]  (dd = d & 31, dgroup = d >> 5)
__device__ float   g_knot_t[8 * 64 * 32];
__device__ float2  g_tab_t[8 * 65 * 32];             // (slope, intercept)

__device__ __forceinline__ uint32_t smem_u32(const void* p) {
    uint32_t a;
    asm("{ .reg .u64 t; cvta.to.shared.u64 t, %1; cvt.u32.u64 %0, t; }"
        : "=r"(a) : "l"(p));
    return a;
}

// =====================================================================
// Kernel 1: PWL table build (blocks 0..63, transposed output layout)
//           + Wc fp16 convert (blocks 64..191).
// =====================================================================
__global__ __launch_bounds__(128)
void prep_kernel(const float* __restrict__ W1,
                 const float* __restrict__ b1,
                 const float* __restrict__ W2,
                 const float* __restrict__ b2,
                 const float* __restrict__ Wc)
{
    const int bid = blockIdx.x;

    if (bid >= 64) {
        const float4* W4 = reinterpret_cast<const float4*>(Wc);
        int idx = (bid - 64) * 128 + threadIdx.x;
        float4 f = W4[idx];
        __half2 h0 = __float22half2_rn(make_float2(f.x, f.y));
        __half2 h1 = __float22half2_rn(make_float2(f.z, f.w));
        uint2 pk;
        pk.x = *reinterpret_cast<uint32_t*>(&h0);
        pk.y = *reinterpret_cast<uint32_t*>(&h1);
        *reinterpret_cast<uint2*>(&g_wc[idx * 4]) = pk;
        return;
    }

    const int w    = threadIdx.x >> 5;
    const int lane = threadIdx.x & 31;
    const int d    = bid * 4 + w;
    const int dg   = d >> 5;            // dgroup 0..7
    const int dd   = d & 31;
    const int kbase = dg * 64 * 32;     // g_knot_t base
    const int tbase = dg * 65 * 32;     // g_tab_t base

    __shared__ float s_t[4][64], s_ds[4][64], s_di[4][64];
    __shared__ float s_kt[4][64], s_kds[4][64], s_kdi[4][64];

    float t[2], ds[2], di[2];
    float bs = 0.0f, bi = 0.0f;
    #pragma unroll
    for (int i = 0; i < 2; i++) {
        const int h  = lane + i * 32;
        const float w1 = W1[d * H_HID + h];
        const float bb = b1[d * H_HID + h];
        const float w2 = W2[d * H_HID + h];
        if (w1 != 0.0f) {
            t[i]  = -bb / w1;
            ds[i] = fabsf(w1) * w2;
            di[i] = (w1 > 0.0f) ? (w2 * bb) : (-w2 * bb);
            if (w1 < 0.0f) { bs += w1 * w2; bi += w2 * bb; }
        } else {
            t[i]  = __int_as_float(0x7f800000);
            ds[i] = 0.0f;
            di[i] = 0.0f;
            bi   += w2 * fmaxf(bb, 0.0f);
        }
        s_t[w][h]  = t[i];
        s_ds[w][h] = ds[i];
        s_di[w][h] = di[i];
    }
    #pragma unroll
    for (int off = 16; off >= 1; off >>= 1) {
        bs += __shfl_xor_sync(0xffffffffu, bs, off);
        bi += __shfl_xor_sync(0xffffffffu, bi, off);
    }
    bi += b2[d];

    __syncwarp();
    int r0 = 0, r1 = 0;
    const float t0 = t[0], t1 = t[1];
    #pragma unroll 16
    for (int j = 0; j < 64; j++) {
        float tj = s_t[w][j];
        r0 += (tj < t0) || (tj == t0 && j < lane);
        r1 += (tj < t1) || (tj == t1 && j < lane + 32);
    }
    s_kt[w][r0]  = t0;  s_kds[w][r0] = ds[0]; s_kdi[w][r0] = di[0];
    s_kt[w][r1]  = t1;  s_kds[w][r1] = ds[1]; s_kdi[w][r1] = di[1];
    __syncwarp();

    const float v0s = s_kds[w][2 * lane],     v1s = s_kds[w][2 * lane + 1];
    const float v0i = s_kdi[w][2 * lane],     v1i = s_kdi[w][2 * lane + 1];
    float incs = v0s + v1s, inci = v0i + v1i;
    const float ps = incs, pi = inci;
    #pragma unroll
    for (int off = 1; off < 32; off <<= 1) {
        float as_ = __shfl_up_sync(0xffffffffu, incs, off);
        float ai_ = __shfl_up_sync(0xffffffffu, inci, off);
        if (lane >= off) { incs += as_; inci += ai_; }
    }
    const float exs = incs - ps, exi = inci - pi;

    // transposed writes: [idx][dd]
    if (lane == 0)
        g_tab_t[tbase + 0 * 32 + dd] = make_float2(bs, bi);
    g_tab_t[tbase + (2 * lane + 1) * 32 + dd] =
        make_float2(bs + exs + v0s, bi + exi + v0i);
    g_tab_t[tbase + (2 * lane + 2) * 32 + dd] =
        make_float2(bs + incs, bi + inci);
    g_knot_t[kbase + (2 * lane) * 32 + dd]     = s_kt[w][2 * lane];
    g_knot_t[kbase + (2 * lane + 1) * 32 + dd] = s_kt[w][2 * lane + 1];
}

// =====================================================================
// Kernel 2: eval u — transposed tables end-to-end:
//  fill:   consecutive tid -> consecutive gmem addr (coalesced LDG)
//          and bank = dd (conflict-free STS)
//  search: bank = dd for every data-dependent access (conflict-free)
//  tail:   one LDS.64 (slope,intercept) per element, conflict-free
// grid = (64 rowchunks x 8 dgroups) = 512 CTAs, 512 threads, 4 CTA/SM.
// =====================================================================
__global__ __launch_bounds__(512)
void eval_u_kernel(const float* __restrict__ x)
{
    __shared__ float  skt[64 * 32];    // knots  [j][dd]   8KB
    __shared__ float2 stab[65 * 32];   // (slope,inter) [k][dd] 16.25KB

    const int tid = threadIdx.x;
    const int dgr = blockIdx.y;
    const int d0  = dgr * 32;

    // coalesced fills
    #pragma unroll
    for (int i = tid; i < 64 * 32; i += 512)
        skt[i] = g_knot_t[dgr * 64 * 32 + i];
    for (int i = tid; i < 65 * 32; i += 512)
        stab[i] = g_tab_t[dgr * 65 * 32 + i];
    __syncthreads();

    const int dd  = tid & 31;
    const int bl  = tid >> 5;
    const int d   = d0 + dd;
    const int rowbase = blockIdx.x * 256;

    // level-1 pivots in registers: knot[8g+7]
    float pv[8];
    #pragma unroll
    for (int g = 0; g < 8; g++) pv[g] = skt[(g * 8 + 7) * 32 + dd];

    #pragma unroll
    for (int batch = 0; batch < 2; batch++) {
        const int rb = rowbase + batch * 128 + bl;
        float xv[8];
        #pragma unroll
        for (int j = 0; j < 8; j++)
            xv[j] = __ldg(&x[(size_t)(rb + j * 16) * D_FEAT + d]);

        int lo[8];
        #pragma unroll
        for (int j = 0; j < 8; j++) {
            const float xj = xv[j];
            int g = 0;
            #pragma unroll
            for (int gg = 0; gg < 8; gg++) g += (pv[gg] < xj);
            const int gm = ((g < 8) ? g : 7) << 3;
            int l2 = (skt[(gm + 3) * 32 + dd] < xj) ? 4 : 0;
            l2 += (skt[(gm + l2 + 1) * 32 + dd] < xj) ? 2 : 0;
            l2 += (skt[(gm + l2) * 32 + dd] < xj) ? 1 : 0;
            lo[j] = (g < 8) ? (gm + l2) : 64;
        }
        #pragma unroll
        for (int j = 0; j < 8; j++) {
            const float2 si = stab[lo[j] * 32 + dd];
            float u = fmaf(si.x, xv[j], si.y);
            g_u[(size_t)(rb + j * 16) * D_FEAT + d] = __float2half(u);
        }
    }
}

// =====================================================================
// Kernel 3: GEMM out = u @ Wc^T + bc, M=128 x N=256 x K=256 (R11 —
// at the legacy-HMMA throughput wall; unchanged).
// 256 threads = 8 warps (2m x 4n), warp tile 64x64, 4-stage prefetch.
// =====================================================================
#define CH      64
#define CH_PAD  72
#define A_ST_H  (128 * CH_PAD)
#define B_ST_H  (256 * CH_PAD)
#define N_STAGE 4
#define GEMM_SMEM_BYTES ((A_ST_H + B_ST_H) * 2 * N_STAGE)   // 221184
#define GTHREADS 256

__device__ __forceinline__ void cp16(uint32_t dst, const void* src) {
    asm volatile("cp.async.cg.shared.global [%0], [%1], 16;"
                 :: "r"(dst), "l"(src));
}
#define CP_COMMIT() asm volatile("cp.async.commit_group;" ::: "memory")
#define CP_WAIT(n)  asm volatile("cp.async.wait_group %0;" :: "n"(n) : "memory")

__device__ __forceinline__ void ldsm_x4(uint32_t* r, uint32_t addr) {
    asm volatile("ldmatrix.sync.aligned.m8n8.x4.shared.b16 {%0,%1,%2,%3}, [%4];"
                 : "=r"(r[0]), "=r"(r[1]), "=r"(r[2]), "=r"(r[3]) : "r"(addr));
}
__device__ __forceinline__ void mma_16816(float* c, const uint32_t* a,
                                          const uint32_t* b) {
    asm volatile(
        "mma.sync.aligned.m16n8k16.row.col.f32.f16.f16.f32 "
        "{%0,%1,%2,%3}, {%4,%5,%6,%7}, {%8,%9}, {%0,%1,%2,%3};"
        : "+f"(c[0]), "+f"(c[1]), "+f"(c[2]), "+f"(c[3])
        : "r"(a[0]), "r"(a[1]), "r"(a[2]), "r"(a[3]), "r"(b[0]), "r"(b[1]));
}

struct GemmCtx {
    uint32_t as_u32, bs_u32;
    const __half* Asrc;
    int tid;
};

__device__ __forceinline__ void issue_chunk(const GemmCtx& g, int c, int st) {
    #pragma unroll
    for (int i = 0; i < 4; i++) {
        int idx = g.tid + i * GTHREADS;
        int row = idx >> 3, k8 = idx & 7;
        cp16(g.as_u32 + (uint32_t)((st * A_ST_H + row * CH_PAD + k8 * 8) * 2),
             g.Asrc + row * D_FEAT + c * CH + k8 * 8);
    }
    #pragma unroll
    for (int i = 0; i < 8; i++) {
        int idx = g.tid + i * GTHREADS;
        int row = idx >> 3, k8 = idx & 7;
        cp16(g.bs_u32 + (uint32_t)((st * B_ST_H + row * CH_PAD + k8 * 8) * 2),
             g_wc + row * D_FEAT + c * CH + k8 * 8);
    }
}

__global__ __launch_bounds__(GTHREADS, 1)
void gemm_kernel(const float* __restrict__ bc, float* __restrict__ out)
{
    extern __shared__ __half smem[];
    __half* As = smem;
    __half* Bs = smem + N_STAGE * A_ST_H;

    const int tid = threadIdx.x;
    const int wid = tid >> 5;
    const int lid = tid & 31;
    const int m0  = blockIdx.x * 128;

    GemmCtx g;
    g.as_u32 = smem_u32(As);
    g.bs_u32 = smem_u32(Bs);
    g.Asrc   = g_u + (size_t)m0 * D_FEAT;
    g.tid    = tid;

    issue_chunk(g, 0, 0); CP_COMMIT();
    issue_chunk(g, 1, 1); CP_COMMIT();
    issue_chunk(g, 2, 2); CP_COMMIT();
    issue_chunk(g, 3, 3); CP_COMMIT();

    const int warp_m = wid >> 2;   // 0..1
    const int warp_n = wid & 3;    // 0..3

    const int a_row = warp_m * 64 + (lid & 15);
    const uint32_t a_lane = g.as_u32
        + (uint32_t)((a_row * CH_PAD + ((lid >> 4) << 3)) * 2);
    const int b_row = warp_n * 64 + (((lid >> 4) & 1) << 3) + (lid & 7);
    const uint32_t b_lane = g.bs_u32
        + (uint32_t)((b_row * CH_PAD + (((lid >> 3) & 1) << 3)) * 2);

    float acc[4][8][4];
    #pragma unroll
    for (int i = 0; i < 4; i++)
        #pragma unroll
        for (int j = 0; j < 8; j++)
            #pragma unroll
            for (int q = 0; q < 4; q++) acc[i][j][q] = 0.0f;

    #pragma unroll
    for (int c = 0; c < 4; c++) {
        if      (c == 0) { CP_WAIT(3); }
        else if (c == 1) { CP_WAIT(2); }
        else if (c == 2) { CP_WAIT(1); }
        else             { CP_WAIT(0); }
        __syncthreads();

        const uint32_t a_st = a_lane + (uint32_t)(c * A_ST_H * 2);
        const uint32_t b_st = b_lane + (uint32_t)(c * B_ST_H * 2);

        #pragma unroll
        for (int ks = 0; ks < 4; ks++) {
            const uint32_t kb = (uint32_t)(ks * 32);
            uint32_t afr[4][4];
            #pragma unroll
            for (int tm = 0; tm < 4; tm++)
                ldsm_x4(afr[tm], a_st + (uint32_t)(tm * 16 * CH_PAD * 2) + kb);
            uint32_t bfr[8][2];
            #pragma unroll
            for (int pn = 0; pn < 4; pn++) {
                uint32_t q[4];
                ldsm_x4(q, b_st + (uint32_t)(pn * 16 * CH_PAD * 2) + kb);
                bfr[2 * pn][0]     = q[0];
                bfr[2 * pn][1]     = q[1];
                bfr[2 * pn + 1][0] = q[2];
                bfr[2 * pn + 1][1] = q[3];
            }
            #pragma unroll
            for (int tm = 0; tm < 4; tm++)
                #pragma unroll
                for (int tn = 0; tn < 8; tn++)
                    mma_16816(acc[tm][tn], afr[tm], bfr[tn]);
        }
    }

    const int qr = lid >> 2;
    const int qc = (lid & 3) * 2;
    #pragma unroll
    for (int tn = 0; tn < 8; tn++) {
        const int cb = warp_n * 64 + tn * 8 + qc;
        const float2 bcv = *reinterpret_cast<const float2*>(bc + cb);
        #pragma unroll
        for (int tm = 0; tm < 4; tm++) {
            const int r = m0 + warp_m * 64 + tm * 16 + qr;
            float2 v0, v1;
            v0.x = acc[tm][tn][0] + bcv.x;
            v0.y = acc[tm][tn][1] + bcv.y;
            v1.x = acc[tm][tn][2] + bcv.x;
            v1.y = acc[tm][tn][3] + bcv.y;
            *reinterpret_cast<float2*>(out + (size_t)r * O_OUT + cb) = v0;
            *reinterpret_cast<float2*>(out + (size_t)(r + 8) * O_OUT + cb) = v1;
        }
    }
}

// =====================================================================
// launch
// =====================================================================
extern "C" void kernel_launch(void* const* d_in, const int* in_sizes, int n_in,
                              void* d_out, int out_size)
{
    const float* x  = (const float*)d_in[0];
    const float* W1 = (const float*)d_in[1];
    const float* b1 = (const float*)d_in[2];
    const float* W2 = (const float*)d_in[3];
    const float* b2 = (const float*)d_in[4];
    const float* Wc = (const float*)d_in[5];
    const float* bc = (const float*)d_in[6];
    float* out = (float*)d_out;

    prep_kernel<<<192, 128>>>(W1, b1, W2, b2, Wc);
    eval_u_kernel<<<dim3(B_ROWS / 256, D_FEAT / 32), 512>>>(x);
    gemm_kernel<<<B_ROWS / 128, GTHREADS, GEMM_SMEM_BYTES>>>(bc, out);
}

namespace {
struct AttrInit {
    AttrInit() {
        cudaFuncSetAttribute(gemm_kernel,
                             cudaFuncAttributeMaxDynamicSharedMemorySize,
                             GEMM_SMEM_BYTES);
    }
} g_attr_init;
}